// round 15
// baseline (speedup 1.0000x reference)
#include <cuda_runtime.h>
#include <cuda_bf16.h>
#include <cuda_fp16.h>
#include <math.h>
#include <stdint.h>

#define NN 100000
#define EE 1600000
#define NB_MAX 128

// ---------------- device scratch ----------------
__device__ int    g_cnt[NN];          // zero-init at load; finalize re-zeroes
__device__ int    g_rowptr[NN + 1];
__device__ int    g_col[EE];
__device__ int    g_slot[EE];
__device__ int    g_bsum[NB_MAX];
__device__ float  g_dinv[NN];
__device__ __half g_hs16[(size_t)NN * 64];
__device__ __half g_ag16[(size_t)NN * 64];
__device__ float  g_ag32[(size_t)NN * 64];

// ---------------- preprocessing ----------------
__global__ void hist_kernel(const int* __restrict__ dst, int e) {
    int i = (blockIdx.x * blockDim.x + threadIdx.x) * 2;
    if (i + 1 < e) {
        int d0 = __ldg(&dst[i]);
        int d1 = __ldg(&dst[i + 1]);
        g_slot[i]     = atomicAdd(&g_cnt[d0], 1);
        g_slot[i + 1] = atomicAdd(&g_cnt[d1], 1);
    } else if (i < e) {
        g_slot[i] = atomicAdd(&g_cnt[__ldg(&dst[i])], 1);
    }
}
__global__ void scan_blocks(int n) {
    __shared__ int wsum[32];
    int tid = threadIdx.x, lane = tid & 31, wid = tid >> 5;
    int gid = blockIdx.x * 1024 + tid;
    int v = (gid < n) ? g_cnt[gid] : 0;
    int x = v;
    #pragma unroll
    for (int off = 1; off < 32; off <<= 1) {
        int t = __shfl_up_sync(0xffffffffu, x, off);
        if (lane >= off) x += t;
    }
    if (lane == 31) wsum[wid] = x;
    __syncthreads();
    if (wid == 0) {
        int s = wsum[lane];
        #pragma unroll
        for (int off = 1; off < 32; off <<= 1) {
            int t = __shfl_up_sync(0xffffffffu, s, off);
            if (lane >= off) s += t;
        }
        wsum[lane] = s;
    }
    __syncthreads();
    int incl = x + (wid > 0 ? wsum[wid - 1] : 0);
    if (gid < n) g_rowptr[gid] = incl - v;
    if (tid == 1023) g_bsum[blockIdx.x] = incl;
}
__global__ void finalize_kernel(int n, int nb) {
    __shared__ int sboff[NB_MAX];
    __shared__ int stot;
    int tid = threadIdx.x;
    if (tid < 32) {
        int base = tid * 4;
        int v0 = (base + 0 < nb) ? g_bsum[base + 0] : 0;
        int v1 = (base + 1 < nb) ? g_bsum[base + 1] : 0;
        int v2 = (base + 2 < nb) ? g_bsum[base + 2] : 0;
        int v3 = (base + 3 < nb) ? g_bsum[base + 3] : 0;
        int s0 = v0, s1 = s0 + v1, s2 = s1 + v2, s3 = s2 + v3;
        int c = s3;
        #pragma unroll
        for (int off = 1; off < 32; off <<= 1) {
            int t = __shfl_up_sync(0xffffffffu, c, off);
            if (tid >= off) c += t;
        }
        int excl = c - s3;
        sboff[base + 0] = excl;
        sboff[base + 1] = excl + s0;
        sboff[base + 2] = excl + s1;
        sboff[base + 3] = excl + s2;
        if (tid == 31) stot = c;
    }
    __syncthreads();
    int i = blockIdx.x * blockDim.x + tid;
    if (i < n) {
        g_rowptr[i] += sboff[i >> 10];
        g_dinv[i] = rsqrtf((float)(g_cnt[i] + 1));
        g_cnt[i] = 0;   // reset for next graph replay
    }
    if (blockIdx.x == 0 && tid == 0) g_rowptr[n] = stot;
}
__global__ void scatter_kernel(const int* __restrict__ src,
                               const int* __restrict__ dst, int e) {
    int i = (blockIdx.x * blockDim.x + threadIdx.x) * 2;
    if (i + 1 < e) {
        int d0 = __ldg(&dst[i]);
        int d1 = __ldg(&dst[i + 1]);
        int s0 = __ldg(&src[i]);
        int s1 = __ldg(&src[i + 1]);
        int sl0 = g_slot[i];
        int sl1 = g_slot[i + 1];
        int r0 = g_rowptr[d0];
        int r1 = g_rowptr[d1];
        g_col[r0 + sl0] = s0;
        g_col[r1 + sl1] = s1;
    } else if (i < e) {
        int d = __ldg(&dst[i]);
        g_col[g_rowptr[d] + g_slot[i]] = __ldg(&src[i]);
    }
}

// ---------------- fp16 mma helpers ----------------
__device__ __forceinline__ uint32_t h2_hi(float2 v) {
    __half2 h = __floats2half2_rn(v.x, v.y);
    return *reinterpret_cast<uint32_t*>(&h);
}
__device__ __forceinline__ uint32_t h2_lo(float2 v, uint32_t hbits) {
    __half2 h = *reinterpret_cast<__half2*>(&hbits);
    float2 b = __half22float2(h);
    __half2 l = __floats2half2_rn(v.x - b.x, v.y - b.y);
    return *reinterpret_cast<uint32_t*>(&l);
}
__device__ __forceinline__ void mma_f16(float* c, uint32_t a0, uint32_t a1,
                                        uint32_t a2, uint32_t a3,
                                        uint32_t b0, uint32_t b1) {
    asm volatile(
        "mma.sync.aligned.m16n8k16.row.col.f32.f16.f16.f32 "
        "{%0,%1,%2,%3}, {%4,%5,%6,%7}, {%8,%9}, {%0,%1,%2,%3};"
        : "+f"(c[0]), "+f"(c[1]), "+f"(c[2]), "+f"(c[3])
        : "r"(a0), "r"(a1), "r"(a2), "r"(a3), "r"(b0), "r"(b1));
}
__device__ __forceinline__ void ldsm_x4_trans(uint32_t& r0, uint32_t& r1,
                                              uint32_t& r2, uint32_t& r3, uint32_t a) {
    asm volatile("ldmatrix.sync.aligned.m8n8.x4.trans.shared.b16 {%0,%1,%2,%3}, [%4];"
                 : "=r"(r0), "=r"(r1), "=r"(r2), "=r"(r3) : "r"(a));
}

// ---------------- GEMM: fp16 2-pass (A split, B single) -----------------------
// WARPS warps/CTA, RG row-groups/warp; CTA rows = WARPS*16*RG. RS: epilogue
// multiplies row r by g_dinv[r].
template <int KS, int NT, int RG, int OUTH, int WARPS, int RS>
__global__ void __launch_bounds__(WARPS * 32)
gemm_mma_kernel(const float* __restrict__ X, const float* __restrict__ W,
                void* __restrict__ outv, int M, const float* __restrict__ bias) {
    constexpr int K  = KS * 16;
    constexpr int Nn = NT * 8;
    constexpr int PB = Nn + 8;
    constexpr int MT = WARPS * 16 * RG;
    constexpr int NTHR = WARPS * 32;
    extern __shared__ __half wS[];

    int tid = threadIdx.x, lane = tid & 31, wid = tid >> 5;
    int rowbase = blockIdx.x * MT;

    constexpr int N4 = Nn / 4;
    #pragma unroll
    for (int idx = tid; idx < K * N4; idx += NTHR) {
        int k = idx / N4;
        int n4 = (idx - k * N4) * 4;
        float4 v = __ldg((const float4*)(W + (size_t)k * Nn + n4));
        *(__half2*)(wS + k * PB + n4)     = __floats2half2_rn(v.x, v.y);
        *(__half2*)(wS + k * PB + n4 + 2) = __floats2half2_rn(v.z, v.w);
    }
    __syncthreads();

    int gp = lane >> 2, tig = lane & 3;
    const float* xA[RG];
    const float* xB[RG];
    int rA[RG], rB[RG];
    #pragma unroll
    for (int rg = 0; rg < RG; rg++) {
        rA[rg] = rowbase + wid * (16 * RG) + rg * 16 + gp;
        rB[rg] = rA[rg] + 8;
        xA[rg] = X + (size_t)min(rA[rg], M - 1) * K + tig * 2;
        xB[rg] = X + (size_t)min(rB[rg], M - 1) * K + tig * 2;
    }

    int kRow = (lane & 7) + (((lane >> 3) & 1) << 3);
    int nCol = (lane >> 4) << 3;
    uint32_t wBase = (uint32_t)__cvta_generic_to_shared(wS) +
                     (uint32_t)((kRow * PB + nCol) * 2);

    float acc[RG][NT][4];
    #pragma unroll
    for (int rg = 0; rg < RG; rg++)
        #pragma unroll
        for (int t = 0; t < NT; t++) {
            acc[rg][t][0] = 0.f; acc[rg][t][1] = 0.f;
            acc[rg][t][2] = 0.f; acc[rg][t][3] = 0.f;
        }

    #pragma unroll
    for (int kt = 0; kt < KS; kt++) {
        int ko = kt * 16;
        uint32_t ah[RG][4], al[RG][4];
        #pragma unroll
        for (int rg = 0; rg < RG; rg++) {
            float2 p0 = __ldg((const float2*)(xA[rg] + ko));
            float2 p1 = __ldg((const float2*)(xA[rg] + ko + 8));
            float2 p2 = __ldg((const float2*)(xB[rg] + ko));
            float2 p3 = __ldg((const float2*)(xB[rg] + ko + 8));
            ah[rg][0] = h2_hi(p0); al[rg][0] = h2_lo(p0, ah[rg][0]);
            ah[rg][1] = h2_hi(p2); al[rg][1] = h2_lo(p2, ah[rg][1]);
            ah[rg][2] = h2_hi(p1); al[rg][2] = h2_lo(p1, ah[rg][2]);
            ah[rg][3] = h2_hi(p3); al[rg][3] = h2_lo(p3, ah[rg][3]);
        }
        uint32_t kByte = (uint32_t)(ko * PB * 2);
        #pragma unroll
        for (int nt2 = 0; nt2 < NT / 2; nt2++) {
            uint32_t b0, b1, b2, b3;
            ldsm_x4_trans(b0, b1, b2, b3, wBase + kByte + (uint32_t)(nt2 * 16 * 2));
            #pragma unroll
            for (int rg = 0; rg < RG; rg++) {
                mma_f16(acc[rg][2 * nt2],     ah[rg][0], ah[rg][1], ah[rg][2], ah[rg][3], b0, b1);
                mma_f16(acc[rg][2 * nt2],     al[rg][0], al[rg][1], al[rg][2], al[rg][3], b0, b1);
                mma_f16(acc[rg][2 * nt2 + 1], ah[rg][0], ah[rg][1], ah[rg][2], ah[rg][3], b2, b3);
                mma_f16(acc[rg][2 * nt2 + 1], al[rg][0], al[rg][1], al[rg][2], al[rg][3], b2, b3);
            }
        }
    }

    #pragma unroll
    for (int rg = 0; rg < RG; rg++) {
        float rsA = 1.f, rsB = 1.f;
        if (RS) {
            rsA = __ldg(&g_dinv[min(rA[rg], M - 1)]);
            rsB = __ldg(&g_dinv[min(rB[rg], M - 1)]);
        }
        #pragma unroll
        for (int nt = 0; nt < NT; nt++) {
            int col = nt * 8 + tig * 2;
            if (OUTH) {
                __half* outh = (__half*)outv;
                if (rA[rg] < M)
                    *(__half2*)(outh + (size_t)rA[rg] * Nn + col) =
                        __floats2half2_rn(acc[rg][nt][0] * rsA, acc[rg][nt][1] * rsA);
                if (rB[rg] < M)
                    *(__half2*)(outh + (size_t)rB[rg] * Nn + col) =
                        __floats2half2_rn(acc[rg][nt][2] * rsB, acc[rg][nt][3] * rsB);
            } else {
                float* outf = (float*)outv;
                float bx = 0.f, by = 0.f;
                if (bias) {
                    float2 bv = __ldg((const float2*)&bias[col]);
                    bx = bv.x; by = bv.y;
                }
                if (rA[rg] < M)
                    *(float2*)(outf + (size_t)rA[rg] * Nn + col) =
                        make_float2(acc[rg][nt][0] * rsA + bx, acc[rg][nt][1] * rsA + by);
                if (rB[rg] < M)
                    *(float2*)(outf + (size_t)rB[rg] * Nn + col) =
                        make_float2(acc[rg][nt][2] * rsB + bx, acc[rg][nt][3] * rsB + by);
            }
        }
    }
}

// ---------------- aggregation ----------------
// EDGEDINV=1: rows are raw, multiply each gathered row by dinv[u] (per-edge load).
// EDGEDINV=0: rows are pre-scaled by dinv[u] at the producer; plain sum.
// out[v] = dinv[v]*(sum + self) (+bias, relu, *dinv[v] if OUTSCALE)
template <int OUTH, int RELU, int BIAS, int EDGEDINV, int OUTSCALE>
__global__ void agg_kernel(const __half* __restrict__ hs,
                           const float* __restrict__ bias,
                           void* __restrict__ outv, int n) {
    int w = (blockIdx.x * blockDim.x + threadIdx.x) >> 5;
    if (w >= n) return;
    int lane = threadIdx.x & 31;
    int quarter = lane >> 3;
    int sub = lane & 7;
    const uint4* hrow = (const uint4*)hs;

    float acc[8];
    #pragma unroll
    for (int j = 0; j < 8; j++) acc[j] = 0.f;

    int s = g_rowptr[w], e = g_rowptr[w + 1];
    int i = s + quarter;
    if (i + 4 < e) {
        int u0 = __ldg(&g_col[i]);
        int u1 = __ldg(&g_col[i + 4]);
        while (true) {
            int inext = i + 8;
            bool more = (inext + 4 < e);
            int un0 = 0, un1 = 0;
            if (more) {
                un0 = __ldg(&g_col[inext]);
                un1 = __ldg(&g_col[inext + 4]);
            }
            float d0 = 1.f, d1 = 1.f;
            if (EDGEDINV) {
                d0 = __ldg(&g_dinv[u0]);
                d1 = __ldg(&g_dinv[u1]);
            }
            uint4 v0 = __ldg(&hrow[(size_t)u0 * 8 + sub]);
            uint4 v1 = __ldg(&hrow[(size_t)u1 * 8 + sub]);
            const __half2* h0 = (const __half2*)&v0;
            const __half2* h1 = (const __half2*)&v1;
            #pragma unroll
            for (int j = 0; j < 4; j++) {
                float2 f0 = __half22float2(h0[j]);
                float2 f1 = __half22float2(h1[j]);
                if (EDGEDINV) {
                    acc[2 * j]     += d0 * f0.x + d1 * f1.x;
                    acc[2 * j + 1] += d0 * f0.y + d1 * f1.y;
                } else {
                    acc[2 * j]     += f0.x + f1.x;
                    acc[2 * j + 1] += f0.y + f1.y;
                }
            }
            i = inext;
            if (!more) break;
            u0 = un0; u1 = un1;
        }
    }
    for (; i < e; i += 4) {
        int u = __ldg(&g_col[i]);
        float d = EDGEDINV ? __ldg(&g_dinv[u]) : 1.f;
        uint4 v = __ldg(&hrow[(size_t)u * 8 + sub]);
        const __half2* h = (const __half2*)&v;
        #pragma unroll
        for (int j = 0; j < 4; j++) {
            float2 f = __half22float2(h[j]);
            if (EDGEDINV) {
                acc[2 * j]     += d * f.x;
                acc[2 * j + 1] += d * f.y;
            } else {
                acc[2 * j]     += f.x;
                acc[2 * j + 1] += f.y;
            }
        }
    }
    if (quarter == 0) {   // self-loop
        float dv = EDGEDINV ? __ldg(&g_dinv[w]) : 1.f;
        uint4 v = __ldg(&hrow[(size_t)w * 8 + sub]);
        const __half2* h = (const __half2*)&v;
        #pragma unroll
        for (int j = 0; j < 4; j++) {
            float2 f = __half22float2(h[j]);
            if (EDGEDINV) {
                acc[2 * j]     += dv * f.x;
                acc[2 * j + 1] += dv * f.y;
            } else {
                acc[2 * j]     += f.x;
                acc[2 * j + 1] += f.y;
            }
        }
    }
    #pragma unroll
    for (int j = 0; j < 8; j++) {
        acc[j] += __shfl_xor_sync(0xffffffffu, acc[j], 8);
        acc[j] += __shfl_xor_sync(0xffffffffu, acc[j], 16);
    }
    if (lane < 8) {
        float dv = __ldg(&g_dinv[w]);
        #pragma unroll
        for (int j = 0; j < 8; j++) acc[j] *= dv;
        if (BIAS) {
            float4 b0 = __ldg((const float4*)&bias[sub * 8]);
            float4 b1 = __ldg((const float4*)&bias[sub * 8 + 4]);
            acc[0] += b0.x; acc[1] += b0.y; acc[2] += b0.z; acc[3] += b0.w;
            acc[4] += b1.x; acc[5] += b1.y; acc[6] += b1.z; acc[7] += b1.w;
        }
        if (RELU) {
            #pragma unroll
            for (int j = 0; j < 8; j++) acc[j] = fmaxf(acc[j], 0.f);
        }
        if (OUTSCALE) {
            #pragma unroll
            for (int j = 0; j < 8; j++) acc[j] *= dv;
        }
        if (OUTH) {
            __half2 o[4];
            #pragma unroll
            for (int j = 0; j < 4; j++)
                o[j] = __floats2half2_rn(acc[2 * j], acc[2 * j + 1]);
            ((uint4*)outv)[(size_t)w * 8 + sub] = *(uint4*)o;
        } else {
            float4* of = (float4*)outv;
            of[(size_t)w * 16 + sub * 2]     = make_float4(acc[0], acc[1], acc[2], acc[3]);
            of[(size_t)w * 16 + sub * 2 + 1] = make_float4(acc[4], acc[5], acc[6], acc[7]);
        }
    }
}

// ---------------- host launcher (round-12 order, layers 2/3 pre-scaled) -------
extern "C" void kernel_launch(void* const* d_in, const int* in_sizes, int n_in,
                              void* d_out, int out_size) {
    const float* x  = (const float*)d_in[0];
    const int*   ei = (const int*)d_in[1];
    const float* W1 = (const float*)d_in[2];
    const float* b1 = (const float*)d_in[3];
    const float* W2 = (const float*)d_in[4];
    const float* b2 = (const float*)d_in[5];
    const float* W3 = (const float*)d_in[6];
    const float* b3 = (const float*)d_in[7];
    float* out = (float*)d_out;

    int hid   = in_sizes[3];            // 64
    int odim  = in_sizes[7];            // 112
    int indim = in_sizes[2] / hid;      // 128
    int n     = in_sizes[0] / indim;    // 100000
    int e     = in_sizes[1] / 2;        // 1600000
    const int* src = ei;
    const int* dst = ei + e;

    __half *hs16_p, *ag16_p;
    float  *ag32_p;
    cudaGetSymbolAddress((void**)&hs16_p, g_hs16);
    cudaGetSymbolAddress((void**)&ag16_p, g_ag16);
    cudaGetSymbolAddress((void**)&ag32_p, g_ag32);

    int nb = (n + 1023) / 1024;
    int aggBlocks = (n * 32 + 255) / 256;
    int g128 = (n + 127) / 128;
    int e2Blocks = (e / 2 + 255) / 256 + 1;

    auto smem_sz = [](int K, int Nn) { return K * (Nn + 8) * 2; };

    // gemm1 first (no RS -> CSR-independent), then preproc
    gemm_mma_kernel<8, 8, 2, 1, 4, 0><<<g128, 128, smem_sz(128, 64)>>>(x, W1, hs16_p, n, nullptr);
    hist_kernel<<<e2Blocks, 256>>>(dst, e);
    scan_blocks<<<nb, 1024>>>(n);
    finalize_kernel<<<(n + 255) / 256, 256>>>(n, nb);
    scatter_kernel<<<e2Blocks, 256>>>(src, dst, e);
    // agg1: raw rows, per-edge dinv (as in best-known kernel)
    agg_kernel<0, 1, 1, 1, 0><<<aggBlocks, 256>>>(hs16_p, b1, ag32_p, n);
    // gemm2: epilogue pre-scales rows by dinv (runs after finalize -> dinv ready)
    gemm_mma_kernel<4, 8, 2, 1, 4, 1><<<g128, 128, smem_sz(64, 64)>>>(ag32_p, W2, hs16_p, n, nullptr);
    // agg2: pre-scaled input, no per-edge dinv; output also pre-scaled for agg3
    agg_kernel<1, 1, 1, 0, 1><<<aggBlocks, 256>>>(hs16_p, b2, ag16_p, n);
    // agg3: pre-scaled input, plain sum * dinv[v]
    agg_kernel<0, 0, 0, 0, 0><<<aggBlocks, 256>>>(ag16_p, nullptr, ag32_p, n);
    // gemm3: fp32 out + b3 (8 warps, RG=1 -> MT=128)
    gemm_mma_kernel<4, 14, 1, 0, 8, 0><<<g128, 256, smem_sz(64, 112)>>>(ag32_p, W3, out, n, b3);
}

// round 16
// speedup vs baseline: 1.0434x; 1.0434x over previous
#include <cuda_runtime.h>
#include <cuda_bf16.h>
#include <cuda_fp16.h>
#include <math.h>
#include <stdint.h>

#define NN 100000
#define EE 1600000
#define NB_MAX 128

// ---------------- device scratch ----------------
__device__ int    g_cnt[NN];
__device__ int    g_rowptr[NN + 1];
__device__ int    g_col[EE];
__device__ int    g_slot[EE];
__device__ int    g_bsum[NB_MAX];
__device__ float  g_dinv[NN];
__device__ __half g_hs16[(size_t)NN * 64];
__device__ __half g_ag16[(size_t)NN * 64];
__device__ float  g_ag32[(size_t)NN * 64];

// ---------------- preprocessing (exact round-9 versions) ----------------
__global__ void zero_kernel(int n) {
    int i = blockIdx.x * blockDim.x + threadIdx.x;
    if (i < n) g_cnt[i] = 0;
}
__global__ void hist_kernel(const int* __restrict__ dst, int e) {
    int i = blockIdx.x * blockDim.x + threadIdx.x;
    if (i < e) g_slot[i] = atomicAdd(&g_cnt[__ldg(&dst[i])], 1);
}
__global__ void scan_blocks(int n) {
    __shared__ int wsum[32];
    int tid = threadIdx.x, lane = tid & 31, wid = tid >> 5;
    int gid = blockIdx.x * 1024 + tid;
    int v = (gid < n) ? g_cnt[gid] : 0;
    int x = v;
    #pragma unroll
    for (int off = 1; off < 32; off <<= 1) {
        int t = __shfl_up_sync(0xffffffffu, x, off);
        if (lane >= off) x += t;
    }
    if (lane == 31) wsum[wid] = x;
    __syncthreads();
    if (wid == 0) {
        int s = wsum[lane];
        #pragma unroll
        for (int off = 1; off < 32; off <<= 1) {
            int t = __shfl_up_sync(0xffffffffu, s, off);
            if (lane >= off) s += t;
        }
        wsum[lane] = s;
    }
    __syncthreads();
    int incl = x + (wid > 0 ? wsum[wid - 1] : 0);
    if (gid < n) g_rowptr[gid] = incl - v;
    if (tid == 1023) g_bsum[blockIdx.x] = incl;
}
__global__ void finalize_kernel(int n, int nb) {
    __shared__ int sboff[NB_MAX];
    __shared__ int stot;
    int tid = threadIdx.x;
    if (tid < 32) {
        int base = tid * 4;
        int v0 = (base + 0 < nb) ? g_bsum[base + 0] : 0;
        int v1 = (base + 1 < nb) ? g_bsum[base + 1] : 0;
        int v2 = (base + 2 < nb) ? g_bsum[base + 2] : 0;
        int v3 = (base + 3 < nb) ? g_bsum[base + 3] : 0;
        int s0 = v0, s1 = s0 + v1, s2 = s1 + v2, s3 = s2 + v3;
        int c = s3;
        #pragma unroll
        for (int off = 1; off < 32; off <<= 1) {
            int t = __shfl_up_sync(0xffffffffu, c, off);
            if (tid >= off) c += t;
        }
        int excl = c - s3;
        sboff[base + 0] = excl;
        sboff[base + 1] = excl + s0;
        sboff[base + 2] = excl + s1;
        sboff[base + 3] = excl + s2;
        if (tid == 31) stot = c;
    }
    __syncthreads();
    int i = blockIdx.x * blockDim.x + tid;
    if (i < n) {
        g_rowptr[i] += sboff[i >> 10];
        g_dinv[i] = rsqrtf((float)(g_cnt[i] + 1));
    }
    if (blockIdx.x == 0 && tid == 0) g_rowptr[n] = stot;
}
__global__ void scatter_kernel(const int* __restrict__ src,
                               const int* __restrict__ dst, int e) {
    int i = blockIdx.x * blockDim.x + threadIdx.x;
    if (i < e) {
        int d = __ldg(&dst[i]);
        g_col[g_rowptr[d] + g_slot[i]] = __ldg(&src[i]);
    }
}

// ---------------- fp16 mma helpers ----------------
__device__ __forceinline__ uint32_t h2_hi(float2 v) {
    __half2 h = __floats2half2_rn(v.x, v.y);
    return *reinterpret_cast<uint32_t*>(&h);
}
__device__ __forceinline__ uint32_t h2_lo(float2 v, uint32_t hbits) {
    __half2 h = *reinterpret_cast<__half2*>(&hbits);
    float2 b = __half22float2(h);
    __half2 l = __floats2half2_rn(v.x - b.x, v.y - b.y);
    return *reinterpret_cast<uint32_t*>(&l);
}
__device__ __forceinline__ void mma_f16(float* c, uint32_t a0, uint32_t a1,
                                        uint32_t a2, uint32_t a3,
                                        uint32_t b0, uint32_t b1) {
    asm volatile(
        "mma.sync.aligned.m16n8k16.row.col.f32.f16.f16.f32 "
        "{%0,%1,%2,%3}, {%4,%5,%6,%7}, {%8,%9}, {%0,%1,%2,%3};"
        : "+f"(c[0]), "+f"(c[1]), "+f"(c[2]), "+f"(c[3])
        : "r"(a0), "r"(a1), "r"(a2), "r"(a3), "r"(b0), "r"(b1));
}
__device__ __forceinline__ void ldsm_x4_trans(uint32_t& r0, uint32_t& r1,
                                              uint32_t& r2, uint32_t& r3, uint32_t a) {
    asm volatile("ldmatrix.sync.aligned.m8n8.x4.trans.shared.b16 {%0,%1,%2,%3}, [%4];"
                 : "=r"(r0), "=r"(r1), "=r"(r2), "=r"(r3) : "r"(a));
}

// ---------------- GEMM: fp16 2-pass, A-loads software-pipelined --------------
// Round-9 structure; single change: kt+1's A fragments are prefetched before
// kt's convert+MMA block, hiding the global-load latency behind tensor work.
template <int KS, int NT, int RG, int OUTH>
__global__ void __launch_bounds__(128)
gemm_mma_kernel(const float* __restrict__ X, const float* __restrict__ W,
                void* __restrict__ outv, int M, const float* __restrict__ bias) {
    constexpr int K  = KS * 16;
    constexpr int Nn = NT * 8;
    constexpr int PB = Nn + 8;
    constexpr int MT = 64 * RG;
    extern __shared__ __half wS[];

    int tid = threadIdx.x, lane = tid & 31, wid = tid >> 5;
    int rowbase = blockIdx.x * MT;

    constexpr int N4 = Nn / 4;
    #pragma unroll
    for (int idx = tid; idx < K * N4; idx += 128) {
        int k = idx / N4;
        int n4 = (idx - k * N4) * 4;
        float4 v = __ldg((const float4*)(W + (size_t)k * Nn + n4));
        *(__half2*)(wS + k * PB + n4)     = __floats2half2_rn(v.x, v.y);
        *(__half2*)(wS + k * PB + n4 + 2) = __floats2half2_rn(v.z, v.w);
    }
    __syncthreads();

    int gp = lane >> 2, tig = lane & 3;
    const float* xA[RG];
    const float* xB[RG];
    int rA[RG], rB[RG];
    #pragma unroll
    for (int rg = 0; rg < RG; rg++) {
        rA[rg] = rowbase + wid * (16 * RG) + rg * 16 + gp;
        rB[rg] = rA[rg] + 8;
        xA[rg] = X + (size_t)min(rA[rg], M - 1) * K + tig * 2;
        xB[rg] = X + (size_t)min(rB[rg], M - 1) * K + tig * 2;
    }

    int kRow = (lane & 7) + (((lane >> 3) & 1) << 3);
    int nCol = (lane >> 4) << 3;
    uint32_t wBase = (uint32_t)__cvta_generic_to_shared(wS) +
                     (uint32_t)((kRow * PB + nCol) * 2);

    float acc[RG][NT][4];
    #pragma unroll
    for (int rg = 0; rg < RG; rg++)
        #pragma unroll
        for (int t = 0; t < NT; t++) {
            acc[rg][t][0] = 0.f; acc[rg][t][1] = 0.f;
            acc[rg][t][2] = 0.f; acc[rg][t][3] = 0.f;
        }

    // prologue: load kt=0 fragments
    float2 p[RG][4];
    #pragma unroll
    for (int rg = 0; rg < RG; rg++) {
        p[rg][0] = __ldg((const float2*)(xA[rg]));
        p[rg][1] = __ldg((const float2*)(xA[rg] + 8));
        p[rg][2] = __ldg((const float2*)(xB[rg]));
        p[rg][3] = __ldg((const float2*)(xB[rg] + 8));
    }

    #pragma unroll
    for (int kt = 0; kt < KS; kt++) {
        // prefetch next kt's A fragments (independent of current consume)
        float2 pn[RG][4];
        if (kt + 1 < KS) {
            int ko = (kt + 1) * 16;
            #pragma unroll
            for (int rg = 0; rg < RG; rg++) {
                pn[rg][0] = __ldg((const float2*)(xA[rg] + ko));
                pn[rg][1] = __ldg((const float2*)(xA[rg] + ko + 8));
                pn[rg][2] = __ldg((const float2*)(xB[rg] + ko));
                pn[rg][3] = __ldg((const float2*)(xB[rg] + ko + 8));
            }
        }
        // convert current
        uint32_t ah[RG][4], al[RG][4];
        #pragma unroll
        for (int rg = 0; rg < RG; rg++) {
            ah[rg][0] = h2_hi(p[rg][0]); al[rg][0] = h2_lo(p[rg][0], ah[rg][0]);
            ah[rg][1] = h2_hi(p[rg][2]); al[rg][1] = h2_lo(p[rg][2], ah[rg][1]);
            ah[rg][2] = h2_hi(p[rg][1]); al[rg][2] = h2_lo(p[rg][1], ah[rg][2]);
            ah[rg][3] = h2_hi(p[rg][3]); al[rg][3] = h2_lo(p[rg][3], ah[rg][3]);
        }
        uint32_t kByte = (uint32_t)(kt * 16 * PB * 2);
        #pragma unroll
        for (int nt2 = 0; nt2 < NT / 2; nt2++) {
            uint32_t b0, b1, b2, b3;
            ldsm_x4_trans(b0, b1, b2, b3, wBase + kByte + (uint32_t)(nt2 * 16 * 2));
            #pragma unroll
            for (int rg = 0; rg < RG; rg++) {
                mma_f16(acc[rg][2 * nt2],     ah[rg][0], ah[rg][1], ah[rg][2], ah[rg][3], b0, b1);
                mma_f16(acc[rg][2 * nt2],     al[rg][0], al[rg][1], al[rg][2], al[rg][3], b0, b1);
                mma_f16(acc[rg][2 * nt2 + 1], ah[rg][0], ah[rg][1], ah[rg][2], ah[rg][3], b2, b3);
                mma_f16(acc[rg][2 * nt2 + 1], al[rg][0], al[rg][1], al[rg][2], al[rg][3], b2, b3);
            }
        }
        if (kt + 1 < KS) {
            #pragma unroll
            for (int rg = 0; rg < RG; rg++) {
                p[rg][0] = pn[rg][0]; p[rg][1] = pn[rg][1];
                p[rg][2] = pn[rg][2]; p[rg][3] = pn[rg][3];
            }
        }
    }

    #pragma unroll
    for (int rg = 0; rg < RG; rg++) {
        #pragma unroll
        for (int nt = 0; nt < NT; nt++) {
            int col = nt * 8 + tig * 2;
            if (OUTH) {
                __half* outh = (__half*)outv;
                if (rA[rg] < M)
                    *(__half2*)(outh + (size_t)rA[rg] * Nn + col) =
                        __floats2half2_rn(acc[rg][nt][0], acc[rg][nt][1]);
                if (rB[rg] < M)
                    *(__half2*)(outh + (size_t)rB[rg] * Nn + col) =
                        __floats2half2_rn(acc[rg][nt][2], acc[rg][nt][3]);
            } else {
                float* outf = (float*)outv;
                float bx = 0.f, by = 0.f;
                if (bias) {
                    float2 bv = __ldg((const float2*)&bias[col]);
                    bx = bv.x; by = bv.y;
                }
                if (rA[rg] < M)
                    *(float2*)(outf + (size_t)rA[rg] * Nn + col) =
                        make_float2(acc[rg][nt][0] + bx, acc[rg][nt][1] + by);
                if (rB[rg] < M)
                    *(float2*)(outf + (size_t)rB[rg] * Nn + col) =
                        make_float2(acc[rg][nt][2] + bx, acc[rg][nt][3] + by);
            }
        }
    }
}

// ---------------- aggregation: exact round-9 version ----------------
template <int OUTH, int RELU, int BIAS>
__global__ void agg_kernel(const __half* __restrict__ hs,
                           const float* __restrict__ bias,
                           void* __restrict__ outv, int n) {
    int w = (blockIdx.x * blockDim.x + threadIdx.x) >> 5;
    if (w >= n) return;
    int lane = threadIdx.x & 31;
    int quarter = lane >> 3;
    int sub = lane & 7;
    const uint4* hrow = (const uint4*)hs;

    float acc[8];
    #pragma unroll
    for (int j = 0; j < 8; j++) acc[j] = 0.f;

    int s = g_rowptr[w], e = g_rowptr[w + 1];
    int i = s + quarter;
    for (; i + 4 < e; i += 8) {
        int u0 = __ldg(&g_col[i]);
        int u1 = __ldg(&g_col[i + 4]);
        float d0 = __ldg(&g_dinv[u0]);
        float d1 = __ldg(&g_dinv[u1]);
        uint4 v0 = __ldg(&hrow[(size_t)u0 * 8 + sub]);
        uint4 v1 = __ldg(&hrow[(size_t)u1 * 8 + sub]);
        const __half2* h0 = (const __half2*)&v0;
        const __half2* h1 = (const __half2*)&v1;
        #pragma unroll
        for (int j = 0; j < 4; j++) {
            float2 f0 = __half22float2(h0[j]);
            float2 f1 = __half22float2(h1[j]);
            acc[2 * j]     += d0 * f0.x + d1 * f1.x;
            acc[2 * j + 1] += d0 * f0.y + d1 * f1.y;
        }
    }
    if (i < e) {
        int u = __ldg(&g_col[i]);
        float d = __ldg(&g_dinv[u]);
        uint4 v = __ldg(&hrow[(size_t)u * 8 + sub]);
        const __half2* h = (const __half2*)&v;
        #pragma unroll
        for (int j = 0; j < 4; j++) {
            float2 f = __half22float2(h[j]);
            acc[2 * j]     += d * f.x;
            acc[2 * j + 1] += d * f.y;
        }
    }
    if (quarter == 0) {   // self-loop
        float dv = __ldg(&g_dinv[w]);
        uint4 v = __ldg(&hrow[(size_t)w * 8 + sub]);
        const __half2* h = (const __half2*)&v;
        #pragma unroll
        for (int j = 0; j < 4; j++) {
            float2 f = __half22float2(h[j]);
            acc[2 * j]     += dv * f.x;
            acc[2 * j + 1] += dv * f.y;
        }
    }
    #pragma unroll
    for (int j = 0; j < 8; j++) {
        acc[j] += __shfl_xor_sync(0xffffffffu, acc[j], 8);
        acc[j] += __shfl_xor_sync(0xffffffffu, acc[j], 16);
    }
    if (lane < 8) {
        float dv = __ldg(&g_dinv[w]);
        #pragma unroll
        for (int j = 0; j < 8; j++) acc[j] *= dv;
        if (BIAS) {
            float4 b0 = __ldg((const float4*)&bias[sub * 8]);
            float4 b1 = __ldg((const float4*)&bias[sub * 8 + 4]);
            acc[0] += b0.x; acc[1] += b0.y; acc[2] += b0.z; acc[3] += b0.w;
            acc[4] += b1.x; acc[5] += b1.y; acc[6] += b1.z; acc[7] += b1.w;
        }
        if (RELU) {
            #pragma unroll
            for (int j = 0; j < 8; j++) acc[j] = fmaxf(acc[j], 0.f);
        }
        if (OUTH) {
            __half2 o[4];
            #pragma unroll
            for (int j = 0; j < 4; j++)
                o[j] = __floats2half2_rn(acc[2 * j], acc[2 * j + 1]);
            ((uint4*)outv)[(size_t)w * 8 + sub] = *(uint4*)o;
        } else {
            float4* of = (float4*)outv;
            of[(size_t)w * 16 + sub * 2]     = make_float4(acc[0], acc[1], acc[2], acc[3]);
            of[(size_t)w * 16 + sub * 2 + 1] = make_float4(acc[4], acc[5], acc[6], acc[7]);
        }
    }
}

// ---------------- host launcher (exact round-9 order) ----------------
extern "C" void kernel_launch(void* const* d_in, const int* in_sizes, int n_in,
                              void* d_out, int out_size) {
    const float* x  = (const float*)d_in[0];
    const int*   ei = (const int*)d_in[1];
    const float* W1 = (const float*)d_in[2];
    const float* b1 = (const float*)d_in[3];
    const float* W2 = (const float*)d_in[4];
    const float* b2 = (const float*)d_in[5];
    const float* W3 = (const float*)d_in[6];
    const float* b3 = (const float*)d_in[7];
    float* out = (float*)d_out;

    int hid   = in_sizes[3];            // 64
    int odim  = in_sizes[7];            // 112
    int indim = in_sizes[2] / hid;      // 128
    int n     = in_sizes[0] / indim;    // 100000
    int e     = in_sizes[1] / 2;        // 1600000
    const int* src = ei;
    const int* dst = ei + e;

    __half *hs16_p, *ag16_p;
    float  *ag32_p;
    cudaGetSymbolAddress((void**)&hs16_p, g_hs16);
    cudaGetSymbolAddress((void**)&ag16_p, g_ag16);
    cudaGetSymbolAddress((void**)&ag32_p, g_ag32);

    int nb = (n + 1023) / 1024;
    int aggBlocks = (n * 32 + 255) / 256;
    int g128 = (n + 127) / 128;
    int g64  = (n + 63) / 64;

    auto smem_sz = [](int K, int Nn) { return K * (Nn + 8) * 2; };

    zero_kernel<<<(n + 255) / 256, 256>>>(n);                          // 0
    hist_kernel<<<(e + 255) / 256, 256>>>(dst, e);                     // 1
    scan_blocks<<<nb, 1024>>>(n);                                      // 2
    gemm_mma_kernel<8, 8, 2, 1><<<g128, 128, smem_sz(128, 64)>>>(x, W1, hs16_p, n, nullptr); // 3 <- ncu
    finalize_kernel<<<(n + 255) / 256, 256>>>(n, nb);                  // 4
    scatter_kernel<<<(e + 255) / 256, 256>>>(src, dst, e);             // 5

    agg_kernel<0, 1, 1><<<aggBlocks, 256>>>(hs16_p, b1, ag32_p, n);    // 6
    gemm_mma_kernel<4, 8, 2, 1><<<g128, 128, smem_sz(64, 64)>>>(ag32_p, W2, hs16_p, n, nullptr);
    agg_kernel<1, 1, 1><<<aggBlocks, 256>>>(hs16_p, b2, ag16_p, n);
    agg_kernel<0, 0, 0><<<aggBlocks, 256>>>(ag16_p, nullptr, ag32_p, n);
    gemm_mma_kernel<4, 14, 1, 0><<<g64, 128, smem_sz(64, 112)>>>(ag32_p, W3, out, n, b3);
}